// round 2
// baseline (speedup 1.0000x reference)
#include <cuda_runtime.h>

#define ND 128
#define ED 64
#define IND 320     // 2*ND + ED
#define HID 256
#define TM 64       // edges per CTA
#define ASTRIDE 324 // 16B-aligned rows, ty-groups hit distinct banks
#define NTHREADS 256

typedef unsigned long long ull;

__device__ __forceinline__ ull pack2(float lo, float hi) {
    ull r; asm("mov.b64 %0, {%1, %2};" : "=l"(r) : "f"(lo), "f"(hi)); return r;
}
__device__ __forceinline__ void fma2(ull &d, ull a, ull b) {
    asm("fma.rn.f32x2 %0, %1, %2, %0;" : "+l"(d) : "l"(a), "l"(b));
}
__device__ __forceinline__ float2 unpack2(ull v) {
    float2 f; asm("mov.b64 {%0, %1}, %2;" : "=f"(f.x), "=f"(f.y) : "l"(v)); return f;
}

extern __shared__ float smem[];

__global__ __launch_bounds__(NTHREADS) void edge_update_kernel(
    const float* __restrict__ x,
    const int* __restrict__ ei32,      // edge_index viewed as int32 words
    const float* __restrict__ edge_attr,
    const float* __restrict__ w1, const float* __restrict__ b1,
    const float* __restrict__ w2, const float* __restrict__ b2,
    const float* __restrict__ ln_w, const float* __restrict__ ln_b,
    float* __restrict__ out, int E, int N)
{
    float* As = smem;                  // [TM][ASTRIDE]
    float* Bs = smem + TM * ASTRIDE;   // 32*256 floats; reused for w2 chunks [128][64]

    const int tid  = threadIdx.x;
    const int lane = tid & 31;
    const int warp = tid >> 5;
    const int tx   = tid & 15;
    const int ty   = tid >> 4;
    const int m0   = ty * 4;
    const int e0   = blockIdx.x * TM;

    // ---- dtype detection: int64 buffers have zero odd words (values < 2^31) ----
    unsigned oddbits = 0;
    #pragma unroll
    for (int k = 0; k < 16; k++) oddbits |= (unsigned)ei32[2 * k + 1];
    const int step = (oddbits == 0) ? 2 : 1;   // words per logical index

    // ---------------- Gather: A[m] = [x[dst] | x[src] | edge_attr] ----------------
    #pragma unroll
    for (int r = 0; r < 8; r++) {
        int m = warp * 8 + r;
        int e = e0 + m; if (e >= E) e = E - 1;
        int ss = ei32[(size_t)step * e];            // row 0 = src
        int ds = ei32[(size_t)step * (E + e)];      // row 1 = dst
        ss = min(max(ss, 0), N - 1);
        ds = min(max(ds, 0), N - 1);
        float4 vi = ((const float4*)(x + (size_t)ds * ND))[lane];
        float4 vj = ((const float4*)(x + (size_t)ss * ND))[lane];
        float* Ar = As + m * ASTRIDE;
        ((float4*)Ar)[lane]        = vi;   // cols [0,128)
        ((float4*)(Ar + ND))[lane] = vj;   // cols [128,256)
        if (lane < 16)
            ((float4*)(Ar + 2 * ND))[lane] =
                ((const float4*)(edge_attr + (size_t)e * ED))[lane]; // cols [256,320)
    }

    // ---------------- GEMM1: h = relu(A @ w1 + b1), per-thread 4x16 tile -----------
    ull acc[4][8];
    #pragma unroll
    for (int i = 0; i < 4; i++)
        #pragma unroll
        for (int j = 0; j < 8; j++) acc[i][j] = 0ull;

    for (int kt = 0; kt < IND; kt += 32) {
        __syncthreads();
        const float4* w1f4 = (const float4*)(w1 + (size_t)kt * HID);
        #pragma unroll
        for (int it = 0; it < 8; it++) {
            int q = tid + it * NTHREADS;     // 2048 float4 = [32][256] tile
            ((float4*)Bs)[q] = w1f4[q];
        }
        __syncthreads();
        #pragma unroll 8
        for (int kk = 0; kk < 32; kk++) {
            ull a2[4];
            #pragma unroll
            for (int i = 0; i < 4; i++) {
                float a = As[(m0 + i) * ASTRIDE + kt + kk];
                a2[i] = pack2(a, a);
            }
            const ull* Br = (const ull*)(Bs + kk * HID) + tx * 8;
            #pragma unroll
            for (int j = 0; j < 8; j++) {
                ull b = Br[j];
                fma2(acc[0][j], a2[0], b);
                fma2(acc[1][j], a2[1], b);
                fma2(acc[2][j], a2[2], b);
                fma2(acc[3][j], a2[3], b);
            }
        }
    }

    __syncthreads(); // all A reads done before overwriting with h

    // bias + relu; h overwrites As cols [0,256) (edge_attr at [256,320) preserved)
    const int n0 = tx * 16;
    #pragma unroll
    for (int i = 0; i < 4; i++) {
        float* hr = As + (m0 + i) * ASTRIDE + n0;
        #pragma unroll
        for (int j = 0; j < 8; j++) {
            float2 v = unpack2(acc[i][j]);
            v.x = fmaxf(v.x + b1[n0 + 2 * j],     0.f);
            v.y = fmaxf(v.y + b1[n0 + 2 * j + 1], 0.f);
            ((float2*)hr)[j] = v;
        }
    }

    // ---------------- GEMM2: delta = h @ w2 + b2, per-thread 4x4 tile --------------
    ull acc2[4][2];
    #pragma unroll
    for (int i = 0; i < 4; i++) { acc2[i][0] = 0ull; acc2[i][1] = 0ull; }
    const int n2 = tx * 4;

    for (int kt = 0; kt < HID; kt += 128) {
        __syncthreads(); // h stores done (iter 0); Bs reads done (iter 1)
        const float4* w2f4 = (const float4*)(w2 + (size_t)kt * ED);
        #pragma unroll
        for (int it = 0; it < 8; it++) {
            int q = tid + it * NTHREADS;     // 2048 float4 = [128][64] chunk
            ((float4*)Bs)[q] = w2f4[q];
        }
        __syncthreads();
        #pragma unroll 8
        for (int kk = 0; kk < 128; kk++) {
            ull a2[4];
            #pragma unroll
            for (int i = 0; i < 4; i++) {
                float a = As[(m0 + i) * ASTRIDE + kt + kk];
                a2[i] = pack2(a, a);
            }
            const ull* Br = (const ull*)(Bs + kk * ED) + tx * 2;
            ull bA = Br[0], bB = Br[1];
            #pragma unroll
            for (int i = 0; i < 4; i++) {
                fma2(acc2[i][0], a2[i], bA);
                fma2(acc2[i][1], a2[i], bB);
            }
        }
    }

    // ---------------- Epilogue: residual + LayerNorm(64) + affine ------------------
    float ev[4][4];
    #pragma unroll
    for (int i = 0; i < 4; i++) {
        float2 d0 = unpack2(acc2[i][0]);
        float2 d1 = unpack2(acc2[i][1]);
        const float* ar = As + (m0 + i) * ASTRIDE + 2 * ND + n2; // edge_attr
        ev[i][0] = ar[0] + d0.x + b2[n2 + 0];
        ev[i][1] = ar[1] + d0.y + b2[n2 + 1];
        ev[i][2] = ar[2] + d1.x + b2[n2 + 2];
        ev[i][3] = ar[3] + d1.y + b2[n2 + 3];
    }
    float lw[4], lb[4];
    #pragma unroll
    for (int j = 0; j < 4; j++) { lw[j] = ln_w[n2 + j]; lb[j] = ln_b[n2 + j]; }

    #pragma unroll
    for (int i = 0; i < 4; i++) {
        float s = ev[i][0] + ev[i][1] + ev[i][2] + ev[i][3];
        float q = ev[i][0]*ev[i][0] + ev[i][1]*ev[i][1]
                + ev[i][2]*ev[i][2] + ev[i][3]*ev[i][3];
        #pragma unroll
        for (int off = 1; off < 16; off <<= 1) {  // 16-lane row group = half warp
            s += __shfl_xor_sync(0xffffffffu, s, off);
            q += __shfl_xor_sync(0xffffffffu, q, off);
        }
        float mean = s * 0.015625f;
        float var  = q * 0.015625f - mean * mean;
        float inv  = rsqrtf(var + 1e-5f);
        int e = e0 + m0 + i;
        if (e < E) {
            float4 o;
            o.x = (ev[i][0] - mean) * inv * lw[0] + lb[0];
            o.y = (ev[i][1] - mean) * inv * lw[1] + lb[1];
            o.z = (ev[i][2] - mean) * inv * lw[2] + lb[2];
            o.w = (ev[i][3] - mean) * inv * lw[3] + lb[3];
            *((float4*)(out + (size_t)e * ED + n2)) = o;
        }
    }
}

extern "C" void kernel_launch(void* const* d_in, const int* in_sizes, int n_in,
                              void* d_out, int out_size) {
    const float* x   = (const float*)d_in[0];
    const int*   ei  = (const int*)d_in[1];     // int32 or int64 words; detected on-device
    const float* ea  = (const float*)d_in[2];
    const float* w1  = (const float*)d_in[3];
    const float* b1  = (const float*)d_in[4];
    const float* w2  = (const float*)d_in[5];
    const float* b2  = (const float*)d_in[6];
    const float* lnw = (const float*)d_in[7];
    const float* lnb = (const float*)d_in[8];
    float* out = (float*)d_out;

    int E = in_sizes[1] / 2;   // edge_index has 2*E logical elements
    int N = in_sizes[0] / ND;

    static int smem_set = 0;
    int smem_bytes = (TM * ASTRIDE + 32 * HID) * (int)sizeof(float); // 115712 B
    if (!smem_set) {
        cudaFuncSetAttribute(edge_update_kernel,
                             cudaFuncAttributeMaxDynamicSharedMemorySize, smem_bytes);
        smem_set = 1;
    }

    int grid = (E + TM - 1) / TM;
    edge_update_kernel<<<grid, NTHREADS, smem_bytes>>>(
        x, ei, ea, w1, b1, w2, b2, lnw, lnb, out, E, N);
}

// round 3
// speedup vs baseline: 2.6723x; 2.6723x over previous
#include <cuda_runtime.h>

#define ND 128
#define ED 64
#define IND 320     // 2*ND + ED
#define HID 256
#define TM 64       // edges per CTA
#define ASTRIDE 320
#define NTHREADS 256

typedef unsigned long long ull;

__device__ __forceinline__ ull pack2(float lo, float hi) {
    ull r; asm("mov.b64 %0, {%1, %2};" : "=l"(r) : "f"(lo), "f"(hi)); return r;
}
__device__ __forceinline__ void fma2(ull &d, ull a, ull b) {
    asm("fma.rn.f32x2 %0, %1, %2, %0;" : "+l"(d) : "l"(a), "l"(b));
}
__device__ __forceinline__ float2 unpack2(ull v) {
    float2 f; asm("mov.b64 {%0, %1}, %2;" : "=f"(f.x), "=f"(f.y) : "l"(v)); return f;
}

extern __shared__ float smem[];

__global__ __launch_bounds__(NTHREADS, 2) void edge_update_kernel(
    const float* __restrict__ x,
    const int* __restrict__ ei32,      // edge_index viewed as int32 words
    const float* __restrict__ edge_attr,
    const float* __restrict__ w1, const float* __restrict__ b1,
    const float* __restrict__ w2, const float* __restrict__ b2,
    const float* __restrict__ ln_w, const float* __restrict__ ln_b,
    float* __restrict__ out, int E, int N)
{
    float* As = smem;                  // [TM][ASTRIDE]
    float* Bs = smem + TM * ASTRIDE;   // 32*256 floats; reused for w2 chunks [128][64]

    const int tid  = threadIdx.x;
    const int tx   = tid & 31;         // lane: column group
    const int ty   = tid >> 5;         // warp: owns rows [8ty, 8ty+8)
    const int r0   = ty * 8;
    const int e0   = blockIdx.x * TM;

    // ---- dtype detection: int64 buffers have zero odd words (values < 2^31) ----
    unsigned oddbits = 0;
    #pragma unroll
    for (int k = 0; k < 16; k++) oddbits |= (unsigned)ei32[2 * k + 1];
    const int step = (oddbits == 0) ? 2 : 1;

    // ---------------- Gather: A[m] = [x[dst] | x[src] | edge_attr] ----------------
    #pragma unroll
    for (int r = 0; r < 8; r++) {
        int m = r0 + r;
        int e = e0 + m; if (e >= E) e = E - 1;
        int ss = ei32[(size_t)step * e];            // row 0 = src
        int ds = ei32[(size_t)step * (E + e)];      // row 1 = dst
        ss = min(max(ss, 0), N - 1);
        ds = min(max(ds, 0), N - 1);
        float4 vi = ((const float4*)(x + (size_t)ds * ND))[tx];
        float4 vj = ((const float4*)(x + (size_t)ss * ND))[tx];
        float* Ar = As + m * ASTRIDE;
        ((float4*)Ar)[tx]        = vi;   // cols [0,128)
        ((float4*)(Ar + ND))[tx] = vj;   // cols [128,256)
        if (tx < 16)
            ((float4*)(Ar + 2 * ND))[tx] =
                ((const float4*)(edge_attr + (size_t)e * ED))[tx]; // cols [256,320)
    }

    // ------------ GEMM1: h = relu(A @ w1 + b1); thread tile 8 rows x 8 cols --------
    // thread owns cols {tx*2 + 64j, tx*2 + 64j + 1}, j=0..3  (conflict-free ull reads)
    ull acc[8][4];
    #pragma unroll
    for (int i = 0; i < 8; i++)
        #pragma unroll
        for (int j = 0; j < 4; j++) acc[i][j] = 0ull;

    for (int kt = 0; kt < IND; kt += 32) {
        __syncthreads();
        const float4* w1f4 = (const float4*)(w1 + (size_t)kt * HID);
        #pragma unroll
        for (int it = 0; it < 8; it++) {
            int q = tid + it * NTHREADS;     // 2048 float4 = [32][256] tile
            ((float4*)Bs)[q] = w1f4[q];
        }
        __syncthreads();
        #pragma unroll
        for (int kk4 = 0; kk4 < 32; kk4 += 4) {
            float4 a4[8];
            #pragma unroll
            for (int i = 0; i < 8; i++)
                a4[i] = *(const float4*)(As + (r0 + i) * ASTRIDE + kt + kk4);
            #pragma unroll
            for (int kq = 0; kq < 4; kq++) {
                const ull* Br = (const ull*)(Bs + (kk4 + kq) * HID) + tx;
                ull b0 = Br[0], b1r = Br[32], b2r = Br[64], b3r = Br[96];
                #pragma unroll
                for (int i = 0; i < 8; i++) {
                    float a = (&a4[i].x)[kq];
                    ull aa = pack2(a, a);
                    fma2(acc[i][0], aa, b0);
                    fma2(acc[i][1], aa, b1r);
                    fma2(acc[i][2], aa, b2r);
                    fma2(acc[i][3], aa, b3r);
                }
            }
        }
    }

    // bias + relu; h overwrites As cols [0,256); edge_attr at [256,320) preserved.
    // Stores: 32 lanes x 8B consecutive per (i,j) -> conflict-free.
    {
        float2 bv[4];
        #pragma unroll
        for (int j = 0; j < 4; j++)
            bv[j] = ((const float2*)b1)[tx + 32 * j];
        #pragma unroll
        for (int i = 0; i < 8; i++) {
            float* hr = As + (r0 + i) * ASTRIDE;
            #pragma unroll
            for (int j = 0; j < 4; j++) {
                float2 v = unpack2(acc[i][j]);
                v.x = fmaxf(v.x + bv[j].x, 0.f);
                v.y = fmaxf(v.y + bv[j].y, 0.f);
                ((float2*)hr)[tx + 32 * j] = v;
            }
        }
    }

    // ------------ GEMM2: delta = h @ w2 + b2; thread tile 8 rows x 2 cols ----------
    ull acc2[8];
    #pragma unroll
    for (int i = 0; i < 8; i++) acc2[i] = 0ull;

    for (int kt = 0; kt < HID; kt += 128) {
        __syncthreads(); // h stores visible; Bs reads of previous tile done
        const float4* w2f4 = (const float4*)(w2 + (size_t)kt * ED);
        #pragma unroll
        for (int it = 0; it < 8; it++) {
            int q = tid + it * NTHREADS;     // 2048 float4 = [128][64] chunk
            ((float4*)Bs)[q] = w2f4[q];
        }
        __syncthreads();
        #pragma unroll 4
        for (int kk4 = 0; kk4 < 128; kk4 += 4) {
            float4 a4[8];
            #pragma unroll
            for (int i = 0; i < 8; i++)
                a4[i] = *(const float4*)(As + (r0 + i) * ASTRIDE + kt + kk4);
            #pragma unroll
            for (int kq = 0; kq < 4; kq++) {
                ull b = *((const ull*)(Bs + (kk4 + kq) * ED) + tx);
                #pragma unroll
                for (int i = 0; i < 8; i++) {
                    float a = (&a4[i].x)[kq];
                    fma2(acc2[i], pack2(a, a), b);
                }
            }
        }
    }

    // ---------------- Epilogue: residual + LayerNorm(64) + affine ------------------
    float2 b2v = ((const float2*)b2)[tx];
    float2 lwv = ((const float2*)ln_w)[tx];
    float2 lbv = ((const float2*)ln_b)[tx];

    #pragma unroll
    for (int i = 0; i < 8; i++) {
        float2 d = unpack2(acc2[i]);
        float2 ar = *((const float2*)(As + (r0 + i) * ASTRIDE + 2 * ND) + tx);
        float v0 = ar.x + d.x + b2v.x;
        float v1 = ar.y + d.y + b2v.y;
        float s = v0 + v1;
        float q = v0 * v0 + v1 * v1;
        #pragma unroll
        for (int off = 16; off > 0; off >>= 1) {
            s += __shfl_xor_sync(0xffffffffu, s, off);
            q += __shfl_xor_sync(0xffffffffu, q, off);
        }
        float mean = s * 0.015625f;
        float var  = q * 0.015625f - mean * mean;
        float inv  = rsqrtf(var + 1e-5f);
        int e = e0 + r0 + i;
        if (e < E) {
            float2 o;
            o.x = (v0 - mean) * inv * lwv.x + lbv.x;
            o.y = (v1 - mean) * inv * lwv.y + lbv.y;
            ((float2*)(out + (size_t)e * ED))[tx] = o;
        }
    }
}

extern "C" void kernel_launch(void* const* d_in, const int* in_sizes, int n_in,
                              void* d_out, int out_size) {
    const float* x   = (const float*)d_in[0];
    const int*   ei  = (const int*)d_in[1];
    const float* ea  = (const float*)d_in[2];
    const float* w1  = (const float*)d_in[3];
    const float* b1  = (const float*)d_in[4];
    const float* w2  = (const float*)d_in[5];
    const float* b2  = (const float*)d_in[6];
    const float* lnw = (const float*)d_in[7];
    const float* lnb = (const float*)d_in[8];
    float* out = (float*)d_out;

    int E = in_sizes[1] / 2;
    int N = in_sizes[0] / ND;

    static int smem_set = 0;
    int smem_bytes = (TM * ASTRIDE + 32 * HID) * (int)sizeof(float); // 114688 B
    if (!smem_set) {
        cudaFuncSetAttribute(edge_update_kernel,
                             cudaFuncAttributeMaxDynamicSharedMemorySize, smem_bytes);
        smem_set = 1;
    }

    int grid = (E + TM - 1) / TM;
    edge_update_kernel<<<grid, NTHREADS, smem_bytes>>>(
        x, ei, ea, w1, b1, w2, b2, lnw, lnb, out, E, N);
}

// round 5
// speedup vs baseline: 5.0237x; 1.8799x over previous
#include <cuda_runtime.h>
#include <cstdint>

#define ND 128
#define ED 64
#define HID 256
#define NMAX 100000
#define TM 64          // rows per CTA (edges or nodes)
#define NTHREADS 256

typedef unsigned long long ull;

__device__ __forceinline__ ull pack2(float lo, float hi) {
    ull r; asm("mov.b64 %0, {%1, %2};" : "=l"(r) : "f"(lo), "f"(hi)); return r;
}
__device__ __forceinline__ void fma2(ull &d, ull a, ull b) {
    asm("fma.rn.f32x2 %0, %1, %2, %0;" : "+l"(d) : "l"(a), "l"(b));
}
__device__ __forceinline__ ull add2(ull a, ull b) {
    ull r; asm("add.rn.f32x2 %0, %1, %2;" : "=l"(r) : "l"(a), "l"(b)); return r;
}
__device__ __forceinline__ float2 unpack2(ull v) {
    float2 f; asm("mov.b64 {%0, %1}, %2;" : "=f"(f.x), "=f"(f.y) : "l"(v)); return f;
}

// Per-node precomputed partials: Pa = x@W1a + b1, Pb = x@W1b   (~100 MB each)
__device__ __align__(16) float g_Pa[(size_t)NMAX * HID];
__device__ __align__(16) float g_Pb[(size_t)NMAX * HID];

extern __shared__ float smem[];

// ===================== Kernel 1: node-level precompute ==========================
// grid = ((N+63)/64, 2);  blockIdx.y = 0 -> Pa (+b1), 1 -> Pb
__global__ __launch_bounds__(NTHREADS, 2) void precompute_kernel(
    const float* __restrict__ x,
    const float* __restrict__ w1, const float* __restrict__ b1, int N)
{
    float* Xs = smem;              // [64][128]  32 KB
    float* Bs = smem + TM * ND;    // [64][256]  64 KB (k-chunk of W1a/W1b)

    const int tid = threadIdx.x;
    const int tx  = tid & 31;
    const int ty  = tid >> 5;
    const int r0  = ty * 8;
    const int m0  = blockIdx.x * TM;
    const int half = blockIdx.y;

    int node[8];
    #pragma unroll
    for (int r = 0; r < 8; r++) {
        node[r] = min(m0 + r0 + r, N - 1);
        ((float4*)(Xs + (r0 + r) * ND))[tx] =
            ((const float4*)(x + (size_t)node[r] * ND))[tx];
    }

    ull acc[8][4];
    if (half == 0) {
        ull bv[4];
        #pragma unroll
        for (int j = 0; j < 4; j++) {
            float2 b = ((const float2*)b1)[tx + 32 * j];
            bv[j] = pack2(b.x, b.y);
        }
        #pragma unroll
        for (int i = 0; i < 8; i++)
            #pragma unroll
            for (int j = 0; j < 4; j++) acc[i][j] = bv[j];
    } else {
        #pragma unroll
        for (int i = 0; i < 8; i++)
            #pragma unroll
            for (int j = 0; j < 4; j++) acc[i][j] = 0ull;
    }

    for (int kt = 0; kt < ND; kt += 64) {
        __syncthreads();
        const float4* wf4 = (const float4*)(w1 + (size_t)(half * ND + kt) * HID);
        #pragma unroll
        for (int it = 0; it < 16; it++) {
            int q = tid + it * NTHREADS;   // 4096 float4 = [64][256]
            ((float4*)Bs)[q] = wf4[q];
        }
        __syncthreads();
        #pragma unroll 4
        for (int kk4 = 0; kk4 < 64; kk4 += 4) {
            float4 a4[8];
            #pragma unroll
            for (int i = 0; i < 8; i++)
                a4[i] = *(const float4*)(Xs + (r0 + i) * ND + kt + kk4);
            #pragma unroll
            for (int kq = 0; kq < 4; kq++) {
                const ull* Br = (const ull*)(Bs + (kk4 + kq) * HID) + tx;
                ull b0 = Br[0], b1r = Br[32], b2r = Br[64], b3r = Br[96];
                #pragma unroll
                for (int i = 0; i < 8; i++) {
                    float a = (&a4[i].x)[kq];
                    ull aa = pack2(a, a);
                    fma2(acc[i][0], aa, b0);
                    fma2(acc[i][1], aa, b1r);
                    fma2(acc[i][2], aa, b2r);
                    fma2(acc[i][3], aa, b3r);
                }
            }
        }
    }

    float* P = half ? g_Pb : g_Pa;
    #pragma unroll
    for (int i = 0; i < 8; i++) {
        float2* dst = (float2*)(P + (size_t)node[i] * HID);
        #pragma unroll
        for (int j = 0; j < 4; j++)
            dst[tx + 32 * j] = unpack2(acc[i][j]);
    }
}

// ===================== Kernel 2: per-edge fused MLP + LN ========================
__global__ __launch_bounds__(NTHREADS, 2) void edge_kernel(
    const int* __restrict__ ei32,
    const float* __restrict__ edge_attr,
    const float* __restrict__ w1,       // only rows [256,320) used (W1c)
    const float* __restrict__ w2, const float* __restrict__ b2,
    const float* __restrict__ ln_w, const float* __restrict__ ln_b,
    float* __restrict__ out, int E, int N)
{
    float* Es = smem;                       // [64][64]  edge_attr, 16 KB
    float* Ws = smem + TM * ED;             // [64][256] W1c, then h, 64 KB
    float* Cs = smem + TM * ED + TM * HID;  // [64][64]  W2 k-chunk, 16 KB

    const int tid = threadIdx.x;
    const int tx  = tid & 31;
    const int ty  = tid >> 5;
    const int r0  = ty * 8;
    const int e0  = blockIdx.x * TM;

    // int64/int32 detection (values < 2^31 -> odd words all zero for int64)
    unsigned oddbits = 0;
    #pragma unroll
    for (int k = 0; k < 16; k++) oddbits |= (unsigned)ei32[2 * k + 1];
    const int step = (oddbits == 0) ? 2 : 1;

    // W1c tile: w1 rows [256,320) -> [64][256]
    {
        const float4* wf4 = (const float4*)(w1 + (size_t)(2 * ND) * HID);
        #pragma unroll
        for (int it = 0; it < 16; it++) {
            int q = tid + it * NTHREADS;
            ((float4*)Ws)[q] = wf4[q];
        }
    }

    // per-row: load edge_attr into Es, init acc = Pa[dst] + Pb[src]
    ull acc[8][4];
    #pragma unroll
    for (int r = 0; r < 8; r++) {
        int e = min(e0 + r0 + r, E - 1);
        int ss = ei32[(size_t)step * e];
        int ds = ei32[(size_t)step * (E + e)];
        ss = min(max(ss, 0), N - 1);
        ds = min(max(ds, 0), N - 1);
        if (tx < 16)
            ((float4*)(Es + (r0 + r) * ED))[tx] =
                ((const float4*)(edge_attr + (size_t)e * ED))[tx];
        const ull* pa = (const ull*)(g_Pa + (size_t)ds * HID) + tx;
        const ull* pb = (const ull*)(g_Pb + (size_t)ss * HID) + tx;
        #pragma unroll
        for (int j = 0; j < 4; j++)
            acc[r][j] = add2(pa[32 * j], pb[32 * j]);
    }
    __syncthreads();   // Ws (W1c) visible to all

    // -------- GEMM1 remainder: acc += ea @ W1c  (K = 64) --------
    #pragma unroll 4
    for (int kk4 = 0; kk4 < ED; kk4 += 4) {
        float4 a4[8];
        #pragma unroll
        for (int i = 0; i < 8; i++)
            a4[i] = *(const float4*)(Es + (r0 + i) * ED + kk4);
        #pragma unroll
        for (int kq = 0; kq < 4; kq++) {
            const ull* Br = (const ull*)(Ws + (kk4 + kq) * HID) + tx;
            ull b0 = Br[0], b1r = Br[32], b2r = Br[64], b3r = Br[96];
            #pragma unroll
            for (int i = 0; i < 8; i++) {
                float a = (&a4[i].x)[kq];
                ull aa = pack2(a, a);
                fma2(acc[i][0], aa, b0);
                fma2(acc[i][1], aa, b1r);
                fma2(acc[i][2], aa, b2r);
                fma2(acc[i][3], aa, b3r);
            }
        }
    }
    __syncthreads();   // all W1c reads done; Ws can become h

    // h = relu(acc) -> Ws (own rows; conflict-free float2 stores)
    #pragma unroll
    for (int i = 0; i < 8; i++) {
        float* hr = Ws + (r0 + i) * HID;
        #pragma unroll
        for (int j = 0; j < 4; j++) {
            float2 v = unpack2(acc[i][j]);
            v.x = fmaxf(v.x, 0.f);
            v.y = fmaxf(v.y, 0.f);
            ((float2*)hr)[tx + 32 * j] = v;
        }
    }

    // -------- GEMM2: delta = h @ W2  (K = 256, 4 chunks of 64) --------
    ull acc2[8];
    #pragma unroll
    for (int i = 0; i < 8; i++) acc2[i] = 0ull;

    for (int kt = 0; kt < HID; kt += 64) {
        __syncthreads();   // prev Cs reads done (h stores are own-warp)
        const float4* w2f4 = (const float4*)(w2 + (size_t)kt * ED);
        #pragma unroll
        for (int it = 0; it < 4; it++) {
            int q = tid + it * NTHREADS;   // 1024 float4 = [64][64]
            ((float4*)Cs)[q] = w2f4[q];
        }
        __syncthreads();
        #pragma unroll 4
        for (int kk4 = 0; kk4 < 64; kk4 += 4) {
            float4 a4[8];
            #pragma unroll
            for (int i = 0; i < 8; i++)
                a4[i] = *(const float4*)(Ws + (r0 + i) * HID + kt + kk4);
            #pragma unroll
            for (int kq = 0; kq < 4; kq++) {
                ull b = *((const ull*)(Cs + (kk4 + kq) * ED) + tx);
                #pragma unroll
                for (int i = 0; i < 8; i++) {
                    float a = (&a4[i].x)[kq];
                    fma2(acc2[i], pack2(a, a), b);
                }
            }
        }
    }

    // -------- Epilogue: residual + LayerNorm(64) + affine --------
    float2 b2v = ((const float2*)b2)[tx];
    float2 lwv = ((const float2*)ln_w)[tx];
    float2 lbv = ((const float2*)ln_b)[tx];

    #pragma unroll
    for (int i = 0; i < 8; i++) {
        float2 d  = unpack2(acc2[i]);
        float2 ar = ((const float2*)(Es + (r0 + i) * ED))[tx];
        float v0 = ar.x + d.x + b2v.x;
        float v1 = ar.y + d.y + b2v.y;
        float s = v0 + v1;
        float q = v0 * v0 + v1 * v1;
        #pragma unroll
        for (int off = 16; off > 0; off >>= 1) {
            s += __shfl_xor_sync(0xffffffffu, s, off);
            q += __shfl_xor_sync(0xffffffffu, q, off);
        }
        float mean = s * 0.015625f;
        float var  = q * 0.015625f - mean * mean;
        float inv  = rsqrtf(var + 1e-5f);
        int e = e0 + r0 + i;
        if (e < E) {
            float2 o;
            o.x = (v0 - mean) * inv * lwv.x + lbv.x;
            o.y = (v1 - mean) * inv * lwv.y + lbv.y;
            ((float2*)(out + (size_t)e * ED))[tx] = o;
        }
    }
}

extern "C" void kernel_launch(void* const* d_in, const int* in_sizes, int n_in,
                              void* d_out, int out_size) {
    const float* x   = (const float*)d_in[0];
    const int*   ei  = (const int*)d_in[1];
    const float* ea  = (const float*)d_in[2];
    const float* w1  = (const float*)d_in[3];
    const float* b1  = (const float*)d_in[4];
    const float* w2  = (const float*)d_in[5];
    const float* b2  = (const float*)d_in[6];
    const float* lnw = (const float*)d_in[7];
    const float* lnb = (const float*)d_in[8];
    float* out = (float*)d_out;

    int E = in_sizes[1] / 2;
    int N = in_sizes[0] / ND;

    static int init_done = 0;
    int smem_bytes = (TM * ND + TM * HID) * (int)sizeof(float);          // 98304
    int smem_edge  = (TM * ED + TM * HID + TM * ED) * (int)sizeof(float); // 98304
    if (!init_done) {
        cudaFuncSetAttribute(precompute_kernel,
                             cudaFuncAttributeMaxDynamicSharedMemorySize, smem_bytes);
        cudaFuncSetAttribute(edge_kernel,
                             cudaFuncAttributeMaxDynamicSharedMemorySize, smem_edge);
        init_done = 1;
    }

    dim3 pgrid((N + TM - 1) / TM, 2);
    precompute_kernel<<<pgrid, NTHREADS, smem_bytes>>>(x, w1, b1, N);

    int egrid = (E + TM - 1) / TM;
    edge_kernel<<<egrid, NTHREADS, smem_edge>>>(
        ei, ea, w1, w2, b2, lnw, lnb, out, E, N);
}